// round 11
// baseline (speedup 1.0000x reference)
#include <cuda_runtime.h>
#include <cstdint>

#define FULL_MASK 0xFFFFFFFFu
#define KPL 8                 // timesteps per lane
#define SEG (32 * KPL)        // 256 timesteps per warp-segment
#define WPB 2                 // warps per block
#define PAD_W 9               // padded smem words per lane (conflict-free)

// fast sigmoid via MUFU (EX2 + RCP); rel err ~1e-6, far under 1e-3 tol.
__device__ __forceinline__ float fsigmoid(float x) {
    return __fdividef(1.0f, 1.0f + __expf(-x));
}

// L2 access policy: evict_last (pin input read-set in L2 across replays).
__device__ __forceinline__ uint64_t mk_evict_last() {
    uint64_t p;
    asm("createpolicy.fractional.L2::evict_last.b64 %0, 1.0;" : "=l"(p));
    return p;
}
__device__ __forceinline__ float4 ldg_el4(const float* p, uint64_t pol) {
    float4 v;
    asm volatile("ld.global.L2::cache_hint.v4.f32 {%0,%1,%2,%3}, [%4], %5;"
                 : "=f"(v.x), "=f"(v.y), "=f"(v.z), "=f"(v.w)
                 : "l"(__cvta_generic_to_global(p)), "l"(pol));
    return v;
}
__device__ __forceinline__ float ldg_el(const float* p, uint64_t pol) {
    float v;
    asm volatile("ld.global.L2::cache_hint.f32 %0, [%1], %2;"
                 : "=f"(v) : "l"(__cvta_generic_to_global(p)), "l"(pol));
    return v;
}

// Precomputed per-timestep lambda and gamma (written by prep_kernel).
__device__ __align__(16) float g_lam_tab[16384];
__device__ float g_gamma_c;

__global__ void prep_kernel(const float* __restrict__ raw_gamma,
                            const float* __restrict__ raw_lambd,
                            const int*   __restrict__ p_start,
                            int T)
{
    int t = blockIdx.x * blockDim.x + threadIdx.x;
    if (t == 0) {
        g_gamma_c = 0.98f + 0.02f * fsigmoid(raw_gamma[0]);  // 0.99+0.01*(2s-1)
    }
    int s0 = p_start ? p_start[0] : 0;
    if (t < T) {
        g_lam_tab[t] = fmaf(0.1f, fsigmoid(raw_lambd[s0 + t]), 0.9f);  // 0.9+0.1s
    }
}

// One warp per batch row. Backward affine scan:
//   x_t = A_t * x_{t+1} + B_t,   A_t = g*(1-d_t)*l_t  (shared by both recurrences)
__global__ __launch_bounds__(WPB * 32)
void td_scan_kernel(const float* __restrict__ values,   // [B, T+1]
                    const float* __restrict__ rewards,  // [B, T]
                    const float* __restrict__ dones,    // [B, T]
                    float* __restrict__ out_lam,        // [B, T+1]
                    float* __restrict__ out_sum,        // [B, T]
                    int B, int T)
{
    __shared__ float stage[WPB][32 * PAD_W];

    const int lane = threadIdx.x & 31;
    const int wid  = threadIdx.x >> 5;
    const int row  = blockIdx.x * WPB + wid;
    if (row >= B) return;

    const uint64_t POL = mk_evict_last();
    float* st = stage[wid];
    const float g = g_gamma_c;

    const float* vrow = values  + (size_t)row * (size_t)(T + 1);
    const float* rrow = rewards + (size_t)row * (size_t)T;
    const float* drow = dones   + (size_t)row * (size_t)T;
    float* lrow = out_lam + (size_t)row * (size_t)(T + 1);
    float* srow = out_sum + (size_t)row * (size_t)T;

    const float vlast = ldg_el(vrow + T, POL);
    if (lane == 0) lrow[T] = vlast;

    float c_lam = vlast;
    float c_sum = 0.0f;

    const int nseg = (T + SEG - 1) / SEG;

    for (int s = nseg - 1; s >= 0; --s) {
        const int segb = s * SEG;
        const int base = segb + lane * KPL;
        const bool full = (segb + SEG <= T);

        float A[KPL], Bl[KPL], Bs[KPL];

        if (full) {
            // rewards/dones: evict_last LDG.128 (rows 16B-aligned at base)
            float4 ra = ldg_el4(rrow + base,     POL);
            float4 rb = ldg_el4(rrow + base + 4, POL);
            float4 da = ldg_el4(drow + base,     POL);
            float4 db = ldg_el4(drow + base + 4, POL);

            // lambda table: tiny, shared by all rows
            float4 la = ldg_el4(g_lam_tab + base,     POL);
            float4 lb = ldg_el4(g_lam_tab + base + 4, POL);

            // values window [segb+1 .. segb+SEG]: coalesced scalar evict_last
            // loads, transpose through padded smem to per-lane contiguous regs.
            float vt[8];
            const float* vp = vrow + segb + 1;
            #pragma unroll
            for (int k = 0; k < 8; k++) vt[k] = ldg_el(vp + k * 32 + lane, POL);
            #pragma unroll
            for (int k = 0; k < 8; k++) {
                int i = k * 32 + lane;
                st[(i >> 3) * PAD_W + (i & 7)] = vt[k];
            }
            __syncwarp();
            float vn[KPL];
            #pragma unroll
            for (int j = 0; j < KPL; j++) vn[j] = st[lane * PAD_W + j];
            __syncwarp();

            float r[KPL] = {ra.x, ra.y, ra.z, ra.w, rb.x, rb.y, rb.z, rb.w};
            float d[KPL] = {da.x, da.y, da.z, da.w, db.x, db.y, db.z, db.w};
            float l[KPL] = {la.x, la.y, la.z, la.w, lb.x, lb.y, lb.z, lb.w};

            #pragma unroll
            for (int j = 0; j < KPL; j++) {
                float cont = g - g * d[j];               // gamma*(1-done)
                A[j]  = cont * l[j];
                Bl[j] = fmaf(cont - A[j], vn[j], r[j]);  // cont*(1-l)*vn + r
                Bs[j] = r[j];
            }
        } else {
            #pragma unroll
            for (int j = 0; j < KPL; j++) {
                int t = base + j;
                if (t < T) {
                    float r  = ldg_el(rrow + t, POL);
                    float d  = ldg_el(drow + t, POL);
                    float vn = ldg_el(vrow + t + 1, POL);
                    float l  = g_lam_tab[t];
                    float cont = g - g * d;
                    A[j]  = cont * l;
                    Bl[j] = fmaf(cont - A[j], vn, r);
                    Bs[j] = r;
                } else {
                    A[j] = 1.0f; Bl[j] = 0.0f; Bs[j] = 0.0f;
                }
            }
        }

        // Local composition: S = m_0 ∘ ... ∘ m_{KPL-1}
        float SA = A[KPL - 1], SBl = Bl[KPL - 1], SBs = Bs[KPL - 1];
        #pragma unroll
        for (int j = KPL - 2; j >= 0; --j) {
            SBl = fmaf(A[j], SBl, Bl[j]);
            SBs = fmaf(A[j], SBs, Bs[j]);
            SA  = A[j] * SA;
        }

        // Warp inclusive suffix scan of lane maps.
        #pragma unroll
        for (int len = 1; len < 32; len <<= 1) {
            float Ao  = __shfl_down_sync(FULL_MASK, SA,  len);
            float Blo = __shfl_down_sync(FULL_MASK, SBl, len);
            float Bso = __shfl_down_sync(FULL_MASK, SBs, len);
            if (lane + len < 32) {
                SBl = fmaf(SA, Blo, SBl);
                SBs = fmaf(SA, Bso, SBs);
                SA  = SA * Ao;
            }
        }

        // Incoming state for this lane.
        float nA  = __shfl_down_sync(FULL_MASK, SA,  1);
        float nBl = __shfl_down_sync(FULL_MASK, SBl, 1);
        float nBs = __shfl_down_sync(FULL_MASK, SBs, 1);
        float xl = (lane == 31) ? c_lam : fmaf(nA, c_lam, nBl);
        float xs = (lane == 31) ? c_sum : fmaf(nA, c_sum, nBs);

        // Local expansion.
        float outl[KPL], outs[KPL];
        #pragma unroll
        for (int j = KPL - 1; j >= 0; --j) {
            xl = fmaf(A[j], xl, Bl[j]);
            xs = fmaf(A[j], xs, Bs[j]);
            outl[j] = xl;
            outs[j] = xs;
        }

        if (full) {
            // sum rows aligned -> evict_first STG.128
            float4* s4 = (float4*)(srow + base);
            __stcs(s4,     make_float4(outs[0], outs[1], outs[2], outs[3]));
            __stcs(s4 + 1, make_float4(outs[4], outs[5], outs[6], outs[7]));

            // lam rows misaligned -> transpose via smem, coalesced STG.32
            #pragma unroll
            for (int j = 0; j < KPL; j++) st[lane * PAD_W + j] = outl[j];
            __syncwarp();
            float* lp = lrow + segb;
            #pragma unroll
            for (int k = 0; k < 8; k++) {
                int i = k * 32 + lane;
                __stcs(lp + i, st[(i >> 3) * PAD_W + (i & 7)]);
            }
            __syncwarp();   // staging safe for next segment
        } else {
            #pragma unroll
            for (int j = 0; j < KPL; j++) {
                if (base + j < T) { lrow[base + j] = outl[j]; srow[base + j] = outs[j]; }
            }
        }

        c_lam = __shfl_sync(FULL_MASK, xl, 0);
        c_sum = __shfl_sync(FULL_MASK, xs, 0);
    }
}

extern "C" void kernel_launch(void* const* d_in, const int* in_sizes, int n_in,
                              void* d_out, int out_size)
{
    const float* values    = (const float*)d_in[0];
    const float* rewards   = (const float*)d_in[1];
    const float* dones     = (const float*)d_in[2];
    const float* raw_gamma = (const float*)d_in[3];
    const float* raw_lambd = (const float*)d_in[4];
    const int*   p_start   = (n_in > 5) ? (const int*)d_in[5] : nullptr;

    const int T = in_sizes[4];
    const int B = in_sizes[1] / T;

    float* out_lam = (float*)d_out;                       // B*(T+1)
    float* out_sum = (float*)d_out + (size_t)B * (T + 1); // B*T

    prep_kernel<<<(T + 255) / 256, 256>>>(raw_gamma, raw_lambd, p_start, T);

    const int threads = WPB * 32;
    const int blocks  = (B + WPB - 1) / WPB;

    td_scan_kernel<<<blocks, threads>>>(
        values, rewards, dones, out_lam, out_sum, B, T);
}

// round 12
// speedup vs baseline: 1.0922x; 1.0922x over previous
#include <cuda_runtime.h>
#include <cstdint>

#define FULL_MASK 0xFFFFFFFFu
#define KPL 8                 // timesteps per lane
#define SEG (32 * KPL)        // 256 timesteps per warp-segment
#define WPB 2                 // warps per block
#define PAD_W 9               // padded smem words per lane (conflict-free)

// fast sigmoid via MUFU (EX2 + RCP); rel err ~1e-6, far under 1e-3 tol.
__device__ __forceinline__ float fsigmoid(float x) {
    return __fdividef(1.0f, 1.0f + __expf(-x));
}

// One warp per batch row. Backward affine scan:
//   x_t = A_t * x_{t+1} + B_t,   A_t = g*(1-d_t)*l_t  (shared by both recurrences)
// Single launch. Streaming (__ldcs) one-touch inputs, evict-first (__stcs)
// outputs; lambda/gamma sigmoids inline on the idle MUFU pipe from the
// L1-hot 8KB raw_lambd table.
__global__ __launch_bounds__(WPB * 32)
void td_scan_kernel(const float* __restrict__ values,    // [B, T+1]
                    const float* __restrict__ rewards,   // [B, T]
                    const float* __restrict__ dones,     // [B, T]
                    const float* __restrict__ raw_gamma, // [1]
                    const float* __restrict__ raw_lambd, // [>=T]
                    const int*   __restrict__ p_start,   // [1] or null
                    float* __restrict__ out_lam,         // [B, T+1]
                    float* __restrict__ out_sum,         // [B, T]
                    int B, int T)
{
    __shared__ float stage[WPB][32 * PAD_W];

    const int lane = threadIdx.x & 31;
    const int wid  = threadIdx.x >> 5;
    const int row  = blockIdx.x * WPB + wid;
    if (row >= B) return;

    const int s0 = p_start ? __ldg(p_start) : 0;
    // gamma = 0.99 + 0.01*(2*sig-1) = 0.98 + 0.02*sigmoid  (L1-hot broadcast)
    const float g = 0.98f + 0.02f * fsigmoid(__ldg(raw_gamma));
    const bool lam_vec = ((s0 & 3) == 0);

    float* st = stage[wid];
    const float* vrow = values  + (size_t)row * (size_t)(T + 1);
    const float* rrow = rewards + (size_t)row * (size_t)T;
    const float* drow = dones   + (size_t)row * (size_t)T;
    float* lrow = out_lam + (size_t)row * (size_t)(T + 1);
    float* srow = out_sum + (size_t)row * (size_t)T;

    const float vlast = __ldcs(vrow + T);
    if (lane == 0) lrow[T] = vlast;

    float c_lam = vlast;
    float c_sum = 0.0f;

    const int nseg = (T + SEG - 1) / SEG;

    for (int s = nseg - 1; s >= 0; --s) {
        const int segb = s * SEG;
        const int base = segb + lane * KPL;
        const bool full = (segb + SEG <= T);

        float A[KPL], Bl[KPL], Bs[KPL];

        if (full) {
            // rewards/dones: streaming LDG.128 (rows 16B-aligned at base)
            float4 ra = __ldcs((const float4*)(rrow + base));
            float4 rb = __ldcs((const float4*)(rrow + base) + 1);
            float4 da = __ldcs((const float4*)(drow + base));
            float4 db = __ldcs((const float4*)(drow + base) + 1);

            // raw lambda: L1-hot shared table, default caching
            float xr[KPL];
            if (lam_vec) {
                float4 xa = *((const float4*)(raw_lambd + s0 + base));
                float4 xb = *((const float4*)(raw_lambd + s0 + base) + 1);
                xr[0]=xa.x; xr[1]=xa.y; xr[2]=xa.z; xr[3]=xa.w;
                xr[4]=xb.x; xr[5]=xb.y; xr[6]=xb.z; xr[7]=xb.w;
            } else {
                #pragma unroll
                for (int j = 0; j < KPL; j++) xr[j] = __ldg(raw_lambd + s0 + base + j);
            }

            // values window [segb+1 .. segb+SEG]: coalesced scalar streaming
            // loads, transpose through padded smem to per-lane contiguous regs.
            float vt[8];
            const float* vp = vrow + segb + 1;
            #pragma unroll
            for (int k = 0; k < 8; k++) vt[k] = __ldcs(vp + k * 32 + lane);
            #pragma unroll
            for (int k = 0; k < 8; k++) {
                int i = k * 32 + lane;
                st[(i >> 3) * PAD_W + (i & 7)] = vt[k];
            }
            __syncwarp();
            float vn[KPL];
            #pragma unroll
            for (int j = 0; j < KPL; j++) vn[j] = st[lane * PAD_W + j];
            __syncwarp();

            float r[KPL] = {ra.x, ra.y, ra.z, ra.w, rb.x, rb.y, rb.z, rb.w};
            float d[KPL] = {da.x, da.y, da.z, da.w, db.x, db.y, db.z, db.w};

            #pragma unroll
            for (int j = 0; j < KPL; j++) {
                // lambda = 0.95 + 0.05*(2*sig-1) = 0.9 + 0.1*sigmoid (MUFU)
                float l = fmaf(0.1f, fsigmoid(xr[j]), 0.9f);
                float cont = g - g * d[j];               // gamma*(1-done)
                A[j]  = cont * l;
                Bl[j] = fmaf(cont - A[j], vn[j], r[j]);  // cont*(1-l)*vn + r
                Bs[j] = r[j];
            }
        } else {
            #pragma unroll
            for (int j = 0; j < KPL; j++) {
                int t = base + j;
                if (t < T) {
                    float r  = rrow[t];
                    float d  = drow[t];
                    float vn = vrow[t + 1];
                    float l  = fmaf(0.1f, fsigmoid(__ldg(raw_lambd + s0 + t)), 0.9f);
                    float cont = g - g * d;
                    A[j]  = cont * l;
                    Bl[j] = fmaf(cont - A[j], vn, r);
                    Bs[j] = r;
                } else {
                    A[j] = 1.0f; Bl[j] = 0.0f; Bs[j] = 0.0f;
                }
            }
        }

        // Local composition: S = m_0 ∘ ... ∘ m_{KPL-1}
        float SA = A[KPL - 1], SBl = Bl[KPL - 1], SBs = Bs[KPL - 1];
        #pragma unroll
        for (int j = KPL - 2; j >= 0; --j) {
            SBl = fmaf(A[j], SBl, Bl[j]);
            SBs = fmaf(A[j], SBs, Bs[j]);
            SA  = A[j] * SA;
        }

        // Warp inclusive suffix scan of lane maps.
        #pragma unroll
        for (int len = 1; len < 32; len <<= 1) {
            float Ao  = __shfl_down_sync(FULL_MASK, SA,  len);
            float Blo = __shfl_down_sync(FULL_MASK, SBl, len);
            float Bso = __shfl_down_sync(FULL_MASK, SBs, len);
            if (lane + len < 32) {
                SBl = fmaf(SA, Blo, SBl);
                SBs = fmaf(SA, Bso, SBs);
                SA  = SA * Ao;
            }
        }

        // Incoming state for this lane.
        float nA  = __shfl_down_sync(FULL_MASK, SA,  1);
        float nBl = __shfl_down_sync(FULL_MASK, SBl, 1);
        float nBs = __shfl_down_sync(FULL_MASK, SBs, 1);
        float xl = (lane == 31) ? c_lam : fmaf(nA, c_lam, nBl);
        float xs = (lane == 31) ? c_sum : fmaf(nA, c_sum, nBs);

        // Local expansion.
        float outl[KPL], outs[KPL];
        #pragma unroll
        for (int j = KPL - 1; j >= 0; --j) {
            xl = fmaf(A[j], xl, Bl[j]);
            xs = fmaf(A[j], xs, Bs[j]);
            outl[j] = xl;
            outs[j] = xs;
        }

        if (full) {
            // sum rows aligned -> streaming STG.128
            float4* s4 = (float4*)(srow + base);
            __stcs(s4,     make_float4(outs[0], outs[1], outs[2], outs[3]));
            __stcs(s4 + 1, make_float4(outs[4], outs[5], outs[6], outs[7]));

            // lam rows misaligned -> transpose via smem, coalesced STG.32
            #pragma unroll
            for (int j = 0; j < KPL; j++) st[lane * PAD_W + j] = outl[j];
            __syncwarp();
            float* lp = lrow + segb;
            #pragma unroll
            for (int k = 0; k < 8; k++) {
                int i = k * 32 + lane;
                __stcs(lp + i, st[(i >> 3) * PAD_W + (i & 7)]);
            }
            __syncwarp();   // staging safe for next segment
        } else {
            #pragma unroll
            for (int j = 0; j < KPL; j++) {
                if (base + j < T) { lrow[base + j] = outl[j]; srow[base + j] = outs[j]; }
            }
        }

        c_lam = __shfl_sync(FULL_MASK, xl, 0);
        c_sum = __shfl_sync(FULL_MASK, xs, 0);
    }
}

extern "C" void kernel_launch(void* const* d_in, const int* in_sizes, int n_in,
                              void* d_out, int out_size)
{
    const float* values    = (const float*)d_in[0];
    const float* rewards   = (const float*)d_in[1];
    const float* dones     = (const float*)d_in[2];
    const float* raw_gamma = (const float*)d_in[3];
    const float* raw_lambd = (const float*)d_in[4];
    const int*   p_start   = (n_in > 5) ? (const int*)d_in[5] : nullptr;

    const int T = in_sizes[4];
    const int B = in_sizes[1] / T;

    float* out_lam = (float*)d_out;                       // B*(T+1)
    float* out_sum = (float*)d_out + (size_t)B * (T + 1); // B*T

    const int threads = WPB * 32;
    const int blocks  = (B + WPB - 1) / WPB;

    td_scan_kernel<<<blocks, threads>>>(
        values, rewards, dones, raw_gamma, raw_lambd, p_start,
        out_lam, out_sum, B, T);
}

// round 13
// speedup vs baseline: 1.1068x; 1.0133x over previous
#include <cuda_runtime.h>
#include <cstdint>

#define FULL_MASK 0xFFFFFFFFu
#define KPL 8                 // timesteps per lane
#define SEG (32 * KPL)        // 256 timesteps per warp-segment
#define WPB 4                 // warps per block

// fast sigmoid via MUFU (EX2 + RCP); rel err ~1e-6, far under 1e-3 tol.
__device__ __forceinline__ float fsigmoid(float x) {
    return __fdividef(1.0f, 1.0f + __expf(-x));
}

// One warp per batch row. Backward affine scan:
//   x_t = A_t * x_{t+1} + B_t,   A_t = g*(1-d_t)*l_t  (shared by both recurrences)
// Single launch; streaming inputs (__ldcs), evict-first outputs (__stcs),
// inline MUFU sigmoids from the L1-hot raw_lambd table; XOR-swizzled float4
// smem staging for the two misaligned-row transposes (conflict-free both ways).
__global__ __launch_bounds__(WPB * 32)
void td_scan_kernel(const float* __restrict__ values,    // [B, T+1]
                    const float* __restrict__ rewards,   // [B, T]
                    const float* __restrict__ dones,     // [B, T]
                    const float* __restrict__ raw_gamma, // [1]
                    const float* __restrict__ raw_lambd, // [>=T]
                    const int*   __restrict__ p_start,   // [1] or null
                    float* __restrict__ out_lam,         // [B, T+1]
                    float* __restrict__ out_sum,         // [B, T]
                    int B, int T)
{
    // 64 float4 per warp: slot(D, h) = D*2 + (h ^ ((D>>2)&1)); D = dest lane.
    __shared__ float4 stg[WPB][64];

    const int lane = threadIdx.x & 31;
    const int wid  = threadIdx.x >> 5;
    const int row  = blockIdx.x * WPB + wid;
    if (row >= B) return;

    const int s0 = p_start ? __ldg(p_start) : 0;
    // gamma = 0.99 + 0.01*(2*sig-1) = 0.98 + 0.02*sigmoid
    const float g = 0.98f + 0.02f * fsigmoid(__ldg(raw_gamma));
    const bool lam_vec = ((s0 & 3) == 0);

    float4* sb4 = stg[wid];
    float*  sbw = (float*)sb4;

    // Swizzle constants (per-thread, hoisted):
    //  - vector side: this lane's two float4 slots
    const int lh    = (lane >> 2) & 1;
    const int slotA = lane * 2 + lh;          // holds elements j=0..3
    const int slotB = lane * 2 + (lh ^ 1);    // holds elements j=4..7
    //  - scalar side: word offset of element i = k*32+lane within 32-word row k
    //    (h = (lane>>2)&1 from j=lane&7, w = lane&3; swizzle bit = k&1)
    const int woff_e = ((lane >> 3) << 3) + (lh << 2) + (lane & 3);
    const int woff_o = ((lane >> 3) << 3) + ((lh ^ 1) << 2) + (lane & 3);

    const float* vrow = values  + (size_t)row * (size_t)(T + 1);
    const float* rrow = rewards + (size_t)row * (size_t)T;
    const float* drow = dones   + (size_t)row * (size_t)T;
    float* lrow = out_lam + (size_t)row * (size_t)(T + 1);
    float* srow = out_sum + (size_t)row * (size_t)T;

    const float vlast = __ldcs(vrow + T);
    if (lane == 0) lrow[T] = vlast;

    float c_lam = vlast;
    float c_sum = 0.0f;

    const int nseg = (T + SEG - 1) / SEG;

    for (int s = nseg - 1; s >= 0; --s) {
        const int segb = s * SEG;
        const int base = segb + lane * KPL;
        const bool full = (segb + SEG <= T);

        float A[KPL], Bl[KPL], Bs[KPL];

        if (full) {
            // rewards/dones: streaming LDG.128 (rows 16B-aligned at base)
            float4 ra = __ldcs((const float4*)(rrow + base));
            float4 rb = __ldcs((const float4*)(rrow + base) + 1);
            float4 da = __ldcs((const float4*)(drow + base));
            float4 db = __ldcs((const float4*)(drow + base) + 1);

            // raw lambda: L1-hot shared table
            float xr[KPL];
            if (lam_vec) {
                float4 xa = *((const float4*)(raw_lambd + s0 + base));
                float4 xb = *((const float4*)(raw_lambd + s0 + base) + 1);
                xr[0]=xa.x; xr[1]=xa.y; xr[2]=xa.z; xr[3]=xa.w;
                xr[4]=xb.x; xr[5]=xb.y; xr[6]=xb.z; xr[7]=xb.w;
            } else {
                #pragma unroll
                for (int j = 0; j < KPL; j++) xr[j] = __ldg(raw_lambd + s0 + base + j);
            }

            // values window [segb+1 .. segb+SEG]: coalesced scalar streaming
            // loads -> swizzled smem -> per-lane LDS.128 pair.
            const float* vp = vrow + segb + 1;
            #pragma unroll
            for (int k = 0; k < 8; k++) {
                float v = __ldcs(vp + k * 32 + lane);
                sbw[k * 32 + ((k & 1) ? woff_o : woff_e)] = v;
            }
            __syncwarp();
            float4 va = sb4[slotA];
            float4 vb = sb4[slotB];
            float vn[KPL] = {va.x, va.y, va.z, va.w, vb.x, vb.y, vb.z, vb.w};
            __syncwarp();   // before buffer reuse below

            float r[KPL] = {ra.x, ra.y, ra.z, ra.w, rb.x, rb.y, rb.z, rb.w};
            float d[KPL] = {da.x, da.y, da.z, da.w, db.x, db.y, db.z, db.w};

            #pragma unroll
            for (int j = 0; j < KPL; j++) {
                // lambda = 0.95 + 0.05*(2*sig-1) = 0.9 + 0.1*sigmoid (MUFU)
                float l = fmaf(0.1f, fsigmoid(xr[j]), 0.9f);
                float cont = g - g * d[j];               // gamma*(1-done)
                A[j]  = cont * l;
                Bl[j] = fmaf(cont - A[j], vn[j], r[j]);  // cont*(1-l)*vn + r
                Bs[j] = r[j];
            }
        } else {
            #pragma unroll
            for (int j = 0; j < KPL; j++) {
                int t = base + j;
                if (t < T) {
                    float r  = rrow[t];
                    float d  = drow[t];
                    float vn = vrow[t + 1];
                    float l  = fmaf(0.1f, fsigmoid(__ldg(raw_lambd + s0 + t)), 0.9f);
                    float cont = g - g * d;
                    A[j]  = cont * l;
                    Bl[j] = fmaf(cont - A[j], vn, r);
                    Bs[j] = r;
                } else {
                    A[j] = 1.0f; Bl[j] = 0.0f; Bs[j] = 0.0f;
                }
            }
        }

        // Local composition: S = m_0 ∘ ... ∘ m_{KPL-1}
        float SA = A[KPL - 1], SBl = Bl[KPL - 1], SBs = Bs[KPL - 1];
        #pragma unroll
        for (int j = KPL - 2; j >= 0; --j) {
            SBl = fmaf(A[j], SBl, Bl[j]);
            SBs = fmaf(A[j], SBs, Bs[j]);
            SA  = A[j] * SA;
        }

        // Warp inclusive suffix scan of lane maps.
        #pragma unroll
        for (int len = 1; len < 32; len <<= 1) {
            float Ao  = __shfl_down_sync(FULL_MASK, SA,  len);
            float Blo = __shfl_down_sync(FULL_MASK, SBl, len);
            float Bso = __shfl_down_sync(FULL_MASK, SBs, len);
            if (lane + len < 32) {
                SBl = fmaf(SA, Blo, SBl);
                SBs = fmaf(SA, Bso, SBs);
                SA  = SA * Ao;
            }
        }

        // Incoming state for this lane.
        float nA  = __shfl_down_sync(FULL_MASK, SA,  1);
        float nBl = __shfl_down_sync(FULL_MASK, SBl, 1);
        float nBs = __shfl_down_sync(FULL_MASK, SBs, 1);
        float xl = (lane == 31) ? c_lam : fmaf(nA, c_lam, nBl);
        float xs = (lane == 31) ? c_sum : fmaf(nA, c_sum, nBs);

        // Local expansion.
        float outl[KPL], outs[KPL];
        #pragma unroll
        for (int j = KPL - 1; j >= 0; --j) {
            xl = fmaf(A[j], xl, Bl[j]);
            xs = fmaf(A[j], xs, Bs[j]);
            outl[j] = xl;
            outs[j] = xs;
        }

        if (full) {
            // sum rows aligned -> streaming STG.128
            float4* s4 = (float4*)(srow + base);
            __stcs(s4,     make_float4(outs[0], outs[1], outs[2], outs[3]));
            __stcs(s4 + 1, make_float4(outs[4], outs[5], outs[6], outs[7]));

            // lam rows misaligned -> STS.128 pair into swizzled smem,
            // then coalesced scalar STG.32.
            sb4[slotA] = make_float4(outl[0], outl[1], outl[2], outl[3]);
            sb4[slotB] = make_float4(outl[4], outl[5], outl[6], outl[7]);
            __syncwarp();
            float* lp = lrow + segb;
            #pragma unroll
            for (int k = 0; k < 8; k++) {
                float v = sbw[k * 32 + ((k & 1) ? woff_o : woff_e)];
                __stcs(lp + k * 32 + lane, v);
            }
            __syncwarp();   // staging safe for next segment
        } else {
            #pragma unroll
            for (int j = 0; j < KPL; j++) {
                if (base + j < T) { lrow[base + j] = outl[j]; srow[base + j] = outs[j]; }
            }
        }

        c_lam = __shfl_sync(FULL_MASK, xl, 0);
        c_sum = __shfl_sync(FULL_MASK, xs, 0);
    }
}

extern "C" void kernel_launch(void* const* d_in, const int* in_sizes, int n_in,
                              void* d_out, int out_size)
{
    const float* values    = (const float*)d_in[0];
    const float* rewards   = (const float*)d_in[1];
    const float* dones     = (const float*)d_in[2];
    const float* raw_gamma = (const float*)d_in[3];
    const float* raw_lambd = (const float*)d_in[4];
    const int*   p_start   = (n_in > 5) ? (const int*)d_in[5] : nullptr;

    const int T = in_sizes[4];
    const int B = in_sizes[1] / T;

    float* out_lam = (float*)d_out;                       // B*(T+1)
    float* out_sum = (float*)d_out + (size_t)B * (T + 1); // B*T

    const int threads = WPB * 32;
    const int blocks  = (B + WPB - 1) / WPB;

    td_scan_kernel<<<blocks, threads>>>(
        values, rewards, dones, raw_gamma, raw_lambd, p_start,
        out_lam, out_sum, B, T);
}